// round 3
// baseline (speedup 1.0000x reference)
#include <cuda_runtime.h>
#include <cuda_bf16.h>
#include <math.h>

// ---------------------------------------------------------------------------
// Problem constants
// ---------------------------------------------------------------------------
#define B        8
#define CIN      15          // 3*5 after reshape
#define C1       64          // gating conv / expert conv1 out channels
#define H0       512
#define W0       512
#define H1       256         // after stride-2 7x7
#define W1       256
#define C2       128
#define H2       128         // after stride-2 3x3
#define W2       128
#define NE       3           // experts
#define CONV1_K  (CIN*7*7)   // 735
#define CONV2_K  (C1*3*3)    // 576
#define HEAD1_K  (C2*3*3)    // 1152

// ---------------------------------------------------------------------------
// Device scratch (no allocations allowed)
// ---------------------------------------------------------------------------
__device__ float d_gbuf [B*C1*H1*W1];   // gating conv output (post BN+ReLU)   134 MB
__device__ float d_ebuf1[B*C1*H1*W1];   // expert conv1 output (ReLU)          134 MB
__device__ float d_ebuf2[B*C2*H2*W2];   // expert conv2 output (ReLU)           67 MB
__device__ float d_ebuf3[B*C2*H2*W2];   // expert head1 output (ReLU)           67 MB
__device__ float d_pooled[B*C1];
__device__ int   d_eidx[B];

// ---------------------------------------------------------------------------
// 16-channel FMA helper: wsm row is 16 floats (64B aligned) -> 4x LDS.128
// ---------------------------------------------------------------------------
#define FMA16(v, rowptr) do {                                      \
    const float4* _wv = (const float4*)(rowptr);                   \
    float4 _a = _wv[0], _b = _wv[1], _c = _wv[2], _d = _wv[3];     \
    acc[0]  += (v)*_a.x;  acc[1]  += (v)*_a.y;                     \
    acc[2]  += (v)*_a.z;  acc[3]  += (v)*_a.w;                     \
    acc[4]  += (v)*_b.x;  acc[5]  += (v)*_b.y;                     \
    acc[6]  += (v)*_b.z;  acc[7]  += (v)*_b.w;                     \
    acc[8]  += (v)*_c.x;  acc[9]  += (v)*_c.y;                     \
    acc[10] += (v)*_c.z;  acc[11] += (v)*_c.w;                     \
    acc[12] += (v)*_d.x;  acc[13] += (v)*_d.y;                     \
    acc[14] += (v)*_d.z;  acc[15] += (v)*_d.w;                     \
} while (0)

#define FMA8(v, rowptr) do {                                       \
    const float4* _wv = (const float4*)(rowptr);                   \
    float4 _a = _wv[0], _b = _wv[1];                               \
    acc[0] += (v)*_a.x; acc[1] += (v)*_a.y;                        \
    acc[2] += (v)*_a.z; acc[3] += (v)*_a.w;                        \
    acc[4] += (v)*_b.x; acc[5] += (v)*_b.y;                        \
    acc[6] += (v)*_b.z; acc[7] += (v)*_b.w;                        \
} while (0)

// ---------------------------------------------------------------------------
// Kernel 1: 7x7 stride-2 pad-3 conv, 15 -> 64 channels, 512^2 -> 256^2.
// GATING=true : apply BN affine then ReLU, write d_gbuf.
// GATING=false: index weights by selected expert, ReLU, write d_ebuf1.
// Block: 128 threads = 128 output pixels (half a row), 16 oc per block.
// Grid: (512 tiles, 4 oc groups, 8 batch)
// ---------------------------------------------------------------------------
template <bool GATING>
__global__ void __launch_bounds__(128)
conv7x7_kernel(const float* __restrict__ x,
               const float* __restrict__ w_all,
               const float* __restrict__ bn_gamma,
               const float* __restrict__ bn_beta,
               const float* __restrict__ bn_mean,
               const float* __restrict__ bn_var)
{
    const int tile = blockIdx.x;            // 0..511 (256 rows x 2 halves)
    const int ocg  = blockIdx.y;            // 0..3
    const int b    = blockIdx.z;            // 0..7
    const int oy   = tile >> 1;
    const int ox   = ((tile & 1) << 7) + threadIdx.x;

    const float* w = w_all;
    if (!GATING) w += (long)d_eidx[b] * (C1 * CONV1_K);
    w += (long)ocg * 16 * CONV1_K;

    __shared__ float wsm[CONV1_K][16];      // 47040 B
    for (int idx = threadIdx.x; idx < 16 * CONV1_K; idx += 128) {
        int o = idx / CONV1_K;
        int k = idx - o * CONV1_K;
        wsm[k][o] = w[idx];                 // coalesced global read
    }
    __syncthreads();

    float acc[16];
#pragma unroll
    for (int i = 0; i < 16; i++) acc[i] = 0.f;

    const float* xb = x + (long)b * CIN * H0 * W0;
    for (int ic = 0; ic < CIN; ic++) {
        const float* xc = xb + ic * (H0 * W0);
        for (int ky = 0; ky < 7; ky++) {
            const int iy = oy * 2 + ky - 3;
            const bool rowok = (unsigned)iy < (unsigned)H0;
            const float* xr = xc + iy * W0;
            const int kbase = (ic * 7 + ky) * 7;
#pragma unroll
            for (int kx = 0; kx < 7; kx++) {
                const int ix = ox * 2 + kx - 3;
                float v = (rowok && (unsigned)ix < (unsigned)W0) ? __ldg(xr + ix) : 0.f;
                FMA16(v, wsm[kbase + kx]);
            }
        }
    }

#pragma unroll
    for (int o = 0; o < 16; o++) {
        const int oc = ocg * 16 + o;
        float val = acc[o];
        if (GATING) {
            const float s = bn_gamma[oc] * rsqrtf(bn_var[oc] + 1e-5f);
            val = val * s + (bn_beta[oc] - bn_mean[oc] * s);
        }
        val = fmaxf(val, 0.f);
        float* dst = GATING ? d_gbuf : d_ebuf1;
        dst[((long)(b * C1 + oc) * H1 + oy) * W1 + ox] = val;
    }
}

// ---------------------------------------------------------------------------
// Kernel 2: maxpool 3x3 s2 pad1 (256^2 -> 128^2) + spatial mean, per (b,c).
// ---------------------------------------------------------------------------
__global__ void pool_mean_kernel()
{
    const int bc = blockIdx.x;              // 0..511
    const float* p = d_gbuf + (long)bc * (H1 * W1);
    float sum = 0.f;
    for (int i = threadIdx.x; i < H2 * W2; i += blockDim.x) {
        const int py = i >> 7, px = i & 127;
        float m = -1e30f;
#pragma unroll
        for (int dy = 0; dy < 3; dy++) {
            const int iy = py * 2 - 1 + dy;
            if ((unsigned)iy >= (unsigned)H1) continue;
            const float* row = p + iy * W1;
#pragma unroll
            for (int dx = 0; dx < 3; dx++) {
                const int ix = px * 2 - 1 + dx;
                if ((unsigned)ix < (unsigned)W1) m = fmaxf(m, row[ix]);
            }
        }
        sum += m;
    }
    __shared__ float red[256];
    red[threadIdx.x] = sum;
    __syncthreads();
    for (int s = 128; s > 0; s >>= 1) {
        if (threadIdx.x < s) red[threadIdx.x] += red[threadIdx.x + s];
        __syncthreads();
    }
    if (threadIdx.x == 0) d_pooled[bc] = red[0] * (1.f / (H2 * W2));
}

// ---------------------------------------------------------------------------
// Kernel 3: FC -> logits -> top-1 expert per sample + aux loss.
// ---------------------------------------------------------------------------
__global__ void gate_finalize_kernel(const float* __restrict__ fcw,
                                     const float* __restrict__ fcb,
                                     float* __restrict__ out_loss)
{
    __shared__ float logits[B][NE];
    const int t = threadIdx.x;
    if (t < B * NE) {
        const int b = t / NE, e = t % NE;
        float s = fcb[e];
        const float* pw = fcw + e * C1;
        const float* pp = d_pooled + b * C1;
        for (int i = 0; i < C1; i++) s += pp[i] * pw[i];
        logits[b][e] = s;
    }
    __syncthreads();
    if (t == 0) {
        float dens[NE]  = {0.f, 0.f, 0.f};
        float proxy[NE] = {0.f, 0.f, 0.f};
        for (int b = 0; b < B; b++) {
            int bi = 0;
            for (int e = 1; e < NE; e++)
                if (logits[b][e] > logits[b][bi]) bi = e;   // ties -> lowest idx (matches top_k)
            d_eidx[b] = bi;
            dens[bi] += 1.f / B;
            float mx = logits[b][0];
            for (int e = 1; e < NE; e++) mx = fmaxf(mx, logits[b][e]);
            float ex[NE], sum = 0.f;
            for (int e = 0; e < NE; e++) { ex[e] = expf(logits[b][e] - mx); sum += ex[e]; }
            for (int e = 0; e < NE; e++) proxy[e] += ex[e] / sum * (1.f / B);
        }
        float aux = 0.f;
        for (int e = 0; e < NE; e++) aux += dens[e] * proxy[e];
        aux *= (float)NE;
        *out_loss = 0.01f * aux;
    }
}

// ---------------------------------------------------------------------------
// Kernel 4: 3x3 stride-2 pad-1 conv, 64 -> 128, 256^2 -> 128^2, ReLU.
// Grid: (128 rows, 8 oc groups of 16, 8 batch). Block: 128 thr (full row).
// ---------------------------------------------------------------------------
__global__ void __launch_bounds__(128)
conv2_kernel(const float* __restrict__ w_all)
{
    const int oy  = blockIdx.x;
    const int ocg = blockIdx.y;             // 0..7
    const int b   = blockIdx.z;
    const int ox  = threadIdx.x;

    const float* w = w_all + ((long)d_eidx[b] * C2 + ocg * 16) * CONV2_K;

    __shared__ float wsm[CONV2_K][16];      // 36864 B
    for (int idx = threadIdx.x; idx < 16 * CONV2_K; idx += 128) {
        int o = idx / CONV2_K;
        int k = idx - o * CONV2_K;
        wsm[k][o] = w[idx];
    }
    __syncthreads();

    float acc[16];
#pragma unroll
    for (int i = 0; i < 16; i++) acc[i] = 0.f;

    const float* ib = d_ebuf1 + (long)b * C1 * H1 * W1;
    for (int ic = 0; ic < C1; ic++) {
        const float* xc = ib + ic * (H1 * W1);
#pragma unroll
        for (int ky = 0; ky < 3; ky++) {
            const int iy = oy * 2 + ky - 1;
            const bool rowok = (unsigned)iy < (unsigned)H1;
            const float* xr = xc + iy * W1;
#pragma unroll
            for (int kx = 0; kx < 3; kx++) {
                const int ix = ox * 2 + kx - 1;
                float v = (rowok && (unsigned)ix < (unsigned)W1) ? __ldg(xr + ix) : 0.f;
                FMA16(v, wsm[(ic * 3 + ky) * 3 + kx]);
            }
        }
    }

#pragma unroll
    for (int o = 0; o < 16; o++) {
        const int oc = ocg * 16 + o;
        d_ebuf2[((long)(b * C2 + oc) * H2 + oy) * W2 + ox] = fmaxf(acc[o], 0.f);
    }
}

// ---------------------------------------------------------------------------
// Kernel 5: 3x3 stride-1 pad-1 conv, 128 -> 128, 128^2, + bias, ReLU.
// Grid: (128 rows, 16 oc groups of 8, 8 batch). Block: 128 thr (full row).
// ---------------------------------------------------------------------------
__global__ void __launch_bounds__(128)
head1_kernel(const float* __restrict__ w_all,
             const float* __restrict__ b_all)
{
    const int oy  = blockIdx.x;
    const int ocg = blockIdx.y;             // 0..15
    const int b   = blockIdx.z;
    const int ox  = threadIdx.x;
    const int e   = d_eidx[b];

    const float* w = w_all + ((long)e * C2 + ocg * 8) * HEAD1_K;

    __shared__ float wsm[HEAD1_K][8];       // 36864 B
    for (int idx = threadIdx.x; idx < 8 * HEAD1_K; idx += 128) {
        int o = idx / HEAD1_K;
        int k = idx - o * HEAD1_K;
        wsm[k][o] = w[idx];
    }
    __syncthreads();

    float acc[8];
#pragma unroll
    for (int i = 0; i < 8; i++) acc[i] = 0.f;

    const float* ib = d_ebuf2 + (long)b * C2 * H2 * W2;
    for (int ic = 0; ic < C2; ic++) {
        const float* xc = ib + ic * (H2 * W2);
#pragma unroll
        for (int ky = 0; ky < 3; ky++) {
            const int iy = oy + ky - 1;
            const bool rowok = (unsigned)iy < (unsigned)H2;
            const float* xr = xc + iy * W2;
#pragma unroll
            for (int kx = 0; kx < 3; kx++) {
                const int ix = ox + kx - 1;
                float v = (rowok && (unsigned)ix < (unsigned)W2) ? __ldg(xr + ix) : 0.f;
                FMA8(v, wsm[(ic * 3 + ky) * 3 + kx]);
            }
        }
    }

#pragma unroll
    for (int o = 0; o < 8; o++) {
        const int oc = ocg * 8 + o;
        const float bias = b_all[e * C2 + oc];
        d_ebuf3[((long)(b * C2 + oc) * H2 + oy) * W2 + ox] = fmaxf(acc[o] + bias, 0.f);
    }
}

// ---------------------------------------------------------------------------
// Kernel 6: 1x1 conv 128 -> 5 + bias, scatter into (hm, wh, reg) output layout.
// Grid: (128 rows, 8 batch). Block: 128 thr (full row).
// ---------------------------------------------------------------------------
__global__ void __launch_bounds__(128)
head2_kernel(const float* __restrict__ w_all,
             const float* __restrict__ b_all,
             float* __restrict__ out)
{
    const int oy = blockIdx.x;
    const int b  = blockIdx.y;
    const int ox = threadIdx.x;
    const int e  = d_eidx[b];

    __shared__ float ws[C2][8];             // padded rows: [ic][0..4] used
    for (int idx = threadIdx.x; idx < 5 * C2; idx += 128) {
        int j = idx / C2, ic = idx - j * C2;
        ws[ic][j] = w_all[(long)e * 5 * C2 + idx];
    }
    __syncthreads();

    float acc[5] = {0.f, 0.f, 0.f, 0.f, 0.f};
    const float* ib = d_ebuf3 + (long)b * C2 * H2 * W2 + oy * W2 + ox;
    for (int ic = 0; ic < C2; ic++) {
        const float v = __ldg(ib + ic * (H2 * W2));
        const float4 w4 = *(const float4*)ws[ic];
        acc[0] += v * w4.x;
        acc[1] += v * w4.y;
        acc[2] += v * w4.z;
        acc[3] += v * w4.w;
        acc[4] += v * ws[ic][4];
    }

    const int p = oy * W2 + ox;             // 0..16383
    const int HW = H2 * W2;                 // 16384
    const float* bb = b_all + e * 5;
    // hm = combined[:,0:1]
    out[b * HW + p] = acc[0] + bb[0];
    // wh = combined[:,1:3]
    out[B * HW + (b * 2 + 0) * HW + p] = acc[1] + bb[1];
    out[B * HW + (b * 2 + 1) * HW + p] = acc[2] + bb[2];
    // reg = combined[:,3:5]
    out[3 * B * HW + (b * 2 + 0) * HW + p] = acc[3] + bb[3];
    out[3 * B * HW + (b * 2 + 1) * HW + p] = acc[4] + bb[4];
}

// ---------------------------------------------------------------------------
// Launch
// ---------------------------------------------------------------------------
extern "C" void kernel_launch(void* const* d_in, const int* in_sizes, int n_in,
                              void* d_out, int out_size)
{
    const float* x        = (const float*)d_in[0];
    const float* g_conv_w = (const float*)d_in[1];
    const float* g_gamma  = (const float*)d_in[2];
    const float* g_beta   = (const float*)d_in[3];
    const float* g_mean   = (const float*)d_in[4];
    const float* g_var    = (const float*)d_in[5];
    const float* g_fc_w   = (const float*)d_in[6];
    const float* g_fc_b   = (const float*)d_in[7];
    const float* e_conv1  = (const float*)d_in[8];
    const float* e_conv2  = (const float*)d_in[9];
    const float* e_hw1    = (const float*)d_in[10];
    const float* e_hb1    = (const float*)d_in[11];
    const float* e_hw2    = (const float*)d_in[12];
    const float* e_hb2    = (const float*)d_in[13];
    float* out = (float*)d_out;

    // 1. Gating conv (7x7 s2) + BN + ReLU
    conv7x7_kernel<true><<<dim3(512, 4, B), 128>>>(x, g_conv_w, g_gamma, g_beta, g_mean, g_var);
    // 2. Maxpool + global average
    pool_mean_kernel<<<B * C1, 256>>>();
    // 3. Logits, top-1 expert selection, aux loss (written at end of out)
    gate_finalize_kernel<<<1, 32>>>(g_fc_w, g_fc_b, out + (out_size - 1));
    // 4. Selected expert conv1 (7x7 s2) + ReLU
    conv7x7_kernel<false><<<dim3(512, 4, B), 128>>>(x, e_conv1, nullptr, nullptr, nullptr, nullptr);
    // 5. Expert conv2 (3x3 s2) + ReLU
    conv2_kernel<<<dim3(128, 8, B), 128>>>(e_conv2);
    // 6. Head conv1 (3x3 s1) + bias + ReLU
    head1_kernel<<<dim3(128, 16, B), 128>>>(e_hw1, e_hb1);
    // 7. Head conv2 (1x1) + bias, scattered to (hm, wh, reg)
    head2_kernel<<<dim3(128, B), 128>>>(e_hw2, e_hb2, out);
}

// round 4
// speedup vs baseline: 1.8388x; 1.8388x over previous
#include <cuda_runtime.h>
#include <cuda_bf16.h>
#include <math.h>

// ---------------------------------------------------------------------------
// Problem constants
// ---------------------------------------------------------------------------
#define B        8
#define CIN      15          // 3*5 after reshape
#define C1       64
#define H0       512
#define W0       512
#define H1       256
#define W1       256
#define C2       128
#define H2       128
#define W2       128
#define NE       3
#define CONV1_K  (CIN*7*7)   // 735
#define CONV2_K  (C1*3*3)    // 576
#define HEAD1_K  (C2*3*3)    // 1152

#define XP   520             // padded input:   row index = iy+3 (0..516), col = ix+4 (0..517)
#define E1P  260             // padded ebuf1:   interior rows/cols 1..256
#define E2P  132             // padded ebuf2:   interior rows/cols 1..128

// ---------------------------------------------------------------------------
// Device scratch (zero-initialized at module load; conv kernels only ever
// write interiors, so padding halos stay 0 — border kernels below re-assert
// this cheaply each launch for safety).
// ---------------------------------------------------------------------------
__device__ float d_xpad  [(long)B*CIN*XP*XP];     // 129.8 MB
__device__ float d_gbuf  [(long)B*C1*H1*W1];      // 134 MB   (gating conv out)
__device__ float d_ebuf1p[(long)B*C1*E1P*E1P];    // 138 MB   (expert conv1 out, padded)
__device__ float d_ebuf2p[(long)B*C2*E2P*E2P];    //  71 MB   (expert conv2 out, padded)
__device__ float d_ebuf3 [(long)B*C2*H2*W2];      //  67 MB   (head1 out)
__device__ float d_pooled[B*C1];
__device__ int   d_eidx[B];

// ---------------------------------------------------------------------------
// Packed f32x2 helpers (2 fp32 FMAs per instruction; ptxas never emits FFMA2
// from C++ — must come from PTX fma.rn.f32x2).
// ---------------------------------------------------------------------------
__device__ __forceinline__ unsigned long long pack2(float v) {
    unsigned long long r;
    asm("mov.b64 %0, {%1, %1};" : "=l"(r) : "f"(v));
    return r;
}
__device__ __forceinline__ void ffma2(unsigned long long& d,
                                      unsigned long long a,
                                      unsigned long long b) {
    asm("fma.rn.f32x2 %0, %1, %2, %0;" : "+l"(d) : "l"(a), "l"(b));
}
__device__ __forceinline__ float f2lo(unsigned long long v) {
    return __uint_as_float((unsigned int)v);
}
__device__ __forceinline__ float f2hi(unsigned long long v) {
    return __uint_as_float((unsigned int)(v >> 32));
}

// 16-oc FMA on packed pairs: 4x LDS.128 + 16 FFMA2 (covers TWO pixels' v)
#define FFMA2x8(accA, vv, wp) do {                                  \
    ffma2((accA)[0], (vv), (wp)[0].x); ffma2((accA)[1], (vv), (wp)[0].y); \
    ffma2((accA)[2], (vv), (wp)[1].x); ffma2((accA)[3], (vv), (wp)[1].y); \
    ffma2((accA)[4], (vv), (wp)[2].x); ffma2((accA)[5], (vv), (wp)[2].y); \
    ffma2((accA)[6], (vv), (wp)[3].x); ffma2((accA)[7], (vv), (wp)[3].y); \
} while (0)

// ---------------------------------------------------------------------------
// Kernel 0: build padded input  xpad[b][ic][iy+3][ix+4] = x (or 0)
// ---------------------------------------------------------------------------
__global__ void __launch_bounds__(256)
fill_xpad_kernel(const float* __restrict__ x)
{
    const int row = blockIdx.x;                 // 0 .. B*CIN*XP-1
    const int bc  = row / XP;
    const int r   = row - bc * XP;
    const int iy  = r - 3;
    float* dst = d_xpad + (long)row * XP;
    const float* src = x + (long)bc * H0 * W0 + (long)iy * W0;
    const bool rowok = (unsigned)iy < (unsigned)H0;
    for (int c = threadIdx.x; c < XP; c += 256) {
        const int ix = c - 4;
        dst[c] = (rowok && (unsigned)ix < (unsigned)W0) ? src[ix] : 0.f;
    }
}

// ---------------------------------------------------------------------------
// Border-zero for padded activation buffers (idempotent; halos stay zero)
// ---------------------------------------------------------------------------
template <int P, int LO, int HI>
__global__ void __launch_bounds__(256)
zero_border_kernel(float* __restrict__ buf)
{
    float* p = buf + (long)blockIdx.y * (P * P);
    for (int i = blockIdx.x * 256 + threadIdx.x; i < P * P; i += gridDim.x * 256) {
        const int r = i / P, c = i - r * P;
        if (r < LO || r > HI || c < LO || c > HI) p[i] = 0.f;
    }
}

// ---------------------------------------------------------------------------
// Kernel 1: 7x7 s2 conv, 15 -> 64, 512^2 -> 256^2, from padded input.
// Block 128 thr; each thread computes 2 pixels (ox, ox+128) of one row.
// 16 oc per block.  Grid (256, 4, 8).
// ---------------------------------------------------------------------------
template <bool GATING>
__global__ void __launch_bounds__(128)
conv7x7_kernel(const float* __restrict__ w_all,
               const float* __restrict__ bn_gamma,
               const float* __restrict__ bn_beta,
               const float* __restrict__ bn_mean,
               const float* __restrict__ bn_var)
{
    const int oy  = blockIdx.x;
    const int ocg = blockIdx.y;
    const int b   = blockIdx.z;
    const int ox0 = threadIdx.x;
    const int ox1 = threadIdx.x + 128;

    const float* w = w_all;
    if (!GATING) w += (long)d_eidx[b] * (C1 * CONV1_K);
    w += (long)ocg * 16 * CONV1_K;

    __shared__ __align__(16) float wsm[CONV1_K][16];     // 47040 B
    for (int idx = threadIdx.x; idx < 16 * CONV1_K; idx += 128) {
        int o = idx / CONV1_K;
        int k = idx - o * CONV1_K;
        wsm[k][o] = w[idx];
    }
    __syncthreads();

    unsigned long long acc0[8], acc1[8];
#pragma unroll
    for (int i = 0; i < 8; i++) { acc0[i] = 0ull; acc1[i] = 0ull; }

    const float* xb = d_xpad + (long)b * CIN * XP * XP;
#pragma unroll 1
    for (int ic = 0; ic < CIN; ic++) {
        const float* xc = xb + ic * (XP * XP);
#pragma unroll 1
        for (int ky = 0; ky < 7; ky++) {
            // padded row index = 2*oy + ky ; needed padded cols 2*ox+1 .. 2*ox+7
            const float* row = xc + (2 * oy + ky) * XP;
            const float2* r0 = (const float2*)(row + 2 * ox0);
            const float2* r1 = (const float2*)(row + 2 * ox1);
            const float2 a0 = r0[0], b0 = r0[1], c0 = r0[2], d0 = r0[3];
            const float2 a1 = r1[0], b1 = r1[1], c1 = r1[2], d1 = r1[3];
            const float v0[7] = {a0.y, b0.x, b0.y, c0.x, c0.y, d0.x, d0.y};
            const float v1[7] = {a1.y, b1.x, b1.y, c1.x, c1.y, d1.x, d1.y};
            const int kb = (ic * 7 + ky) * 7;
#pragma unroll
            for (int kx = 0; kx < 7; kx++) {
                const ulonglong2* wp = (const ulonglong2*)wsm[kb + kx];
                const ulonglong2 wv[4] = {wp[0], wp[1], wp[2], wp[3]};
                const unsigned long long vv0 = pack2(v0[kx]);
                const unsigned long long vv1 = pack2(v1[kx]);
                FFMA2x8(acc0, vv0, wv);
                FFMA2x8(acc1, vv1, wv);
            }
        }
    }

#pragma unroll
    for (int o = 0; o < 8; o++) {
        const int oca = ocg * 16 + 2 * o;
        const int ocb = oca + 1;
        float va0 = f2lo(acc0[o]), vb0 = f2hi(acc0[o]);
        float va1 = f2lo(acc1[o]), vb1 = f2hi(acc1[o]);
        if (GATING) {
            const float sa = bn_gamma[oca] * rsqrtf(bn_var[oca] + 1e-5f);
            const float sb = bn_gamma[ocb] * rsqrtf(bn_var[ocb] + 1e-5f);
            const float ba = bn_beta[oca] - bn_mean[oca] * sa;
            const float bb = bn_beta[ocb] - bn_mean[ocb] * sb;
            va0 = va0 * sa + ba;  va1 = va1 * sa + ba;
            vb0 = vb0 * sb + bb;  vb1 = vb1 * sb + bb;
            float* pa = d_gbuf + ((long)(b * C1 + oca) * H1 + oy) * W1;
            float* pb = d_gbuf + ((long)(b * C1 + ocb) * H1 + oy) * W1;
            pa[ox0] = fmaxf(va0, 0.f);  pa[ox1] = fmaxf(va1, 0.f);
            pb[ox0] = fmaxf(vb0, 0.f);  pb[ox1] = fmaxf(vb1, 0.f);
        } else {
            float* pa = d_ebuf1p + ((long)(b * C1 + oca) * E1P + (oy + 1)) * E1P + 1;
            float* pb = d_ebuf1p + ((long)(b * C1 + ocb) * E1P + (oy + 1)) * E1P + 1;
            pa[ox0] = fmaxf(va0, 0.f);  pa[ox1] = fmaxf(va1, 0.f);
            pb[ox0] = fmaxf(vb0, 0.f);  pb[ox1] = fmaxf(vb1, 0.f);
        }
    }
}

// ---------------------------------------------------------------------------
// Kernel 2: maxpool 3x3 s2 pad1 (256^2 -> 128^2) + spatial mean, per (b,c).
// ---------------------------------------------------------------------------
__global__ void pool_mean_kernel()
{
    const int bc = blockIdx.x;
    const float* p = d_gbuf + (long)bc * (H1 * W1);
    float sum = 0.f;
    for (int i = threadIdx.x; i < H2 * W2; i += blockDim.x) {
        const int py = i >> 7, px = i & 127;
        float m = -1e30f;
#pragma unroll
        for (int dy = 0; dy < 3; dy++) {
            const int iy = py * 2 - 1 + dy;
            if ((unsigned)iy >= (unsigned)H1) continue;
            const float* row = p + iy * W1;
#pragma unroll
            for (int dx = 0; dx < 3; dx++) {
                const int ix = px * 2 - 1 + dx;
                if ((unsigned)ix < (unsigned)W1) m = fmaxf(m, row[ix]);
            }
        }
        sum += m;
    }
    __shared__ float red[256];
    red[threadIdx.x] = sum;
    __syncthreads();
    for (int s = 128; s > 0; s >>= 1) {
        if (threadIdx.x < s) red[threadIdx.x] += red[threadIdx.x + s];
        __syncthreads();
    }
    if (threadIdx.x == 0) d_pooled[bc] = red[0] * (1.f / (H2 * W2));
}

// ---------------------------------------------------------------------------
// Kernel 3: FC -> logits -> top-1 expert + aux loss.
// ---------------------------------------------------------------------------
__global__ void gate_finalize_kernel(const float* __restrict__ fcw,
                                     const float* __restrict__ fcb,
                                     float* __restrict__ out_loss)
{
    __shared__ float logits[B][NE];
    const int t = threadIdx.x;
    if (t < B * NE) {
        const int b = t / NE, e = t % NE;
        float s = fcb[e];
        const float* pw = fcw + e * C1;
        const float* pp = d_pooled + b * C1;
        for (int i = 0; i < C1; i++) s += pp[i] * pw[i];
        logits[b][e] = s;
    }
    __syncthreads();
    if (t == 0) {
        float dens[NE]  = {0.f, 0.f, 0.f};
        float proxy[NE] = {0.f, 0.f, 0.f};
        for (int b = 0; b < B; b++) {
            int bi = 0;
            for (int e = 1; e < NE; e++)
                if (logits[b][e] > logits[b][bi]) bi = e;
            d_eidx[b] = bi;
            dens[bi] += 1.f / B;
            float mx = logits[b][0];
            for (int e = 1; e < NE; e++) mx = fmaxf(mx, logits[b][e]);
            float ex[NE], sum = 0.f;
            for (int e = 0; e < NE; e++) { ex[e] = expf(logits[b][e] - mx); sum += ex[e]; }
            for (int e = 0; e < NE; e++) proxy[e] += ex[e] / sum * (1.f / B);
        }
        float aux = 0.f;
        for (int e = 0; e < NE; e++) aux += dens[e] * proxy[e];
        *out_loss = 0.01f * aux * (float)NE;
    }
}

// ---------------------------------------------------------------------------
// Kernel 4: 3x3 s2 conv, 64 -> 128, 256^2 -> 128^2, ReLU.  Padded in+out.
// Block 128 thr = one ox each, 2 output rows per thread (oy0, oy0+1), 16 oc.
// Grid (64, 8, 8).
// ---------------------------------------------------------------------------
__global__ void __launch_bounds__(128)
conv2_kernel(const float* __restrict__ w_all)
{
    const int oy0 = blockIdx.x * 2;
    const int ocg = blockIdx.y;
    const int b   = blockIdx.z;
    const int ox  = threadIdx.x;

    const float* w = w_all + ((long)d_eidx[b] * C2 + ocg * 16) * CONV2_K;
    __shared__ __align__(16) float wsm[CONV2_K][16];     // 36864 B
    for (int idx = threadIdx.x; idx < 16 * CONV2_K; idx += 128) {
        int o = idx / CONV2_K;
        int k = idx - o * CONV2_K;
        wsm[k][o] = w[idx];
    }
    __syncthreads();

    unsigned long long acc0[8], acc1[8];
#pragma unroll
    for (int i = 0; i < 8; i++) { acc0[i] = 0ull; acc1[i] = 0ull; }

    const float* ib = d_ebuf1p + (long)b * C1 * E1P * E1P;
#pragma unroll 1
    for (int ic = 0; ic < C1; ic++) {
        const float* xc = ib + ic * (E1P * E1P);
        // padded rows 2*oy0 .. 2*oy0+4 ; padded cols 2*ox .. 2*ox+2
        float rv[5][3];
#pragma unroll
        for (int r = 0; r < 5; r++) {
            const float2* rp = (const float2*)(xc + (2 * oy0 + r) * E1P + 2 * ox);
            const float2 p = rp[0], q = rp[1];
            rv[r][0] = p.x; rv[r][1] = p.y; rv[r][2] = q.x;
        }
#pragma unroll
        for (int ky = 0; ky < 3; ky++) {
#pragma unroll
            for (int kx = 0; kx < 3; kx++) {
                const ulonglong2* wp = (const ulonglong2*)wsm[(ic * 3 + ky) * 3 + kx];
                const ulonglong2 wv[4] = {wp[0], wp[1], wp[2], wp[3]};
                const unsigned long long vv0 = pack2(rv[ky][kx]);
                const unsigned long long vv1 = pack2(rv[ky + 2][kx]);
                FFMA2x8(acc0, vv0, wv);
                FFMA2x8(acc1, vv1, wv);
            }
        }
    }

#pragma unroll
    for (int o = 0; o < 8; o++) {
        const int oca = ocg * 16 + 2 * o;
        const int ocb = oca + 1;
        float* pa = d_ebuf2p + ((long)(b * C2 + oca) * E2P + (oy0 + 1)) * E2P + (ox + 1);
        float* pb = d_ebuf2p + ((long)(b * C2 + ocb) * E2P + (oy0 + 1)) * E2P + (ox + 1);
        pa[0]   = fmaxf(f2lo(acc0[o]), 0.f);
        pa[E2P] = fmaxf(f2lo(acc1[o]), 0.f);
        pb[0]   = fmaxf(f2hi(acc0[o]), 0.f);
        pb[E2P] = fmaxf(f2hi(acc1[o]), 0.f);
    }
}

// ---------------------------------------------------------------------------
// Kernel 5: 3x3 s1 conv, 128 -> 128, 128^2, + bias, ReLU.  Padded input.
// Block 128 thr = one ox each, 4 output rows per thread, 8 oc.
// Grid (32, 16, 8).
// ---------------------------------------------------------------------------
__global__ void __launch_bounds__(128)
head1_kernel(const float* __restrict__ w_all,
             const float* __restrict__ b_all)
{
    const int oy0 = blockIdx.x * 4;
    const int ocg = blockIdx.y;
    const int b   = blockIdx.z;
    const int ox  = threadIdx.x;
    const int e   = d_eidx[b];

    const float* w = w_all + ((long)e * C2 + ocg * 8) * HEAD1_K;
    __shared__ __align__(16) float wsm[HEAD1_K][8];      // 36864 B
    for (int idx = threadIdx.x; idx < 8 * HEAD1_K; idx += 128) {
        int o = idx / HEAD1_K;
        int k = idx - o * HEAD1_K;
        wsm[k][o] = w[idx];
    }
    __syncthreads();

    unsigned long long acc[4][4];
#pragma unroll
    for (int p = 0; p < 4; p++)
#pragma unroll
        for (int i = 0; i < 4; i++) acc[p][i] = 0ull;

    const float* ib = d_ebuf2p + (long)b * C2 * E2P * E2P;
#pragma unroll 1
    for (int ic = 0; ic < C2; ic++) {
        const float* xc = ib + ic * (E2P * E2P);
        // padded rows oy0 .. oy0+5 ; padded cols ox .. ox+2
        float rv[6][3];
#pragma unroll
        for (int r = 0; r < 6; r++) {
            const float* rp = xc + (oy0 + r) * E2P + ox;
            rv[r][0] = rp[0]; rv[r][1] = rp[1]; rv[r][2] = rp[2];
        }
#pragma unroll
        for (int ky = 0; ky < 3; ky++) {
#pragma unroll
            for (int kx = 0; kx < 3; kx++) {
                const ulonglong2* wp = (const ulonglong2*)wsm[(ic * 3 + ky) * 3 + kx];
                const ulonglong2 wv = wp[0];
                const ulonglong2 wv2 = wp[1];
#pragma unroll
                for (int p = 0; p < 4; p++) {
                    const unsigned long long vv = pack2(rv[p + ky][kx]);
                    ffma2(acc[p][0], vv, wv.x);
                    ffma2(acc[p][1], vv, wv.y);
                    ffma2(acc[p][2], vv, wv2.x);
                    ffma2(acc[p][3], vv, wv2.y);
                }
            }
        }
    }

#pragma unroll
    for (int o = 0; o < 4; o++) {
        const int oca = ocg * 8 + 2 * o;
        const int ocb = oca + 1;
        const float ba = b_all[e * C2 + oca];
        const float bb = b_all[e * C2 + ocb];
        float* pa = d_ebuf3 + ((long)(b * C2 + oca) * H2 + oy0) * W2 + ox;
        float* pb = d_ebuf3 + ((long)(b * C2 + ocb) * H2 + oy0) * W2 + ox;
#pragma unroll
        for (int p = 0; p < 4; p++) {
            pa[p * W2] = fmaxf(f2lo(acc[p][o]) + ba, 0.f);
            pb[p * W2] = fmaxf(f2hi(acc[p][o]) + bb, 0.f);
        }
    }
}

// ---------------------------------------------------------------------------
// Kernel 6: 1x1 conv 128 -> 5 + bias, scatter into (hm, wh, reg) layout.
// ---------------------------------------------------------------------------
__global__ void __launch_bounds__(128)
head2_kernel(const float* __restrict__ w_all,
             const float* __restrict__ b_all,
             float* __restrict__ out)
{
    const int oy = blockIdx.x;
    const int b  = blockIdx.y;
    const int ox = threadIdx.x;
    const int e  = d_eidx[b];

    __shared__ __align__(16) float ws[C2][8];
    for (int idx = threadIdx.x; idx < 5 * C2; idx += 128) {
        int j = idx / C2, ic = idx - j * C2;
        ws[ic][j] = w_all[(long)e * 5 * C2 + idx];
    }
    __syncthreads();

    float acc[5] = {0.f, 0.f, 0.f, 0.f, 0.f};
    const float* ib = d_ebuf3 + (long)b * C2 * H2 * W2 + oy * W2 + ox;
    for (int ic = 0; ic < C2; ic++) {
        const float v = __ldg(ib + ic * (H2 * W2));
        const float4 w4 = *(const float4*)ws[ic];
        acc[0] += v * w4.x;
        acc[1] += v * w4.y;
        acc[2] += v * w4.z;
        acc[3] += v * w4.w;
        acc[4] += v * ws[ic][4];
    }

    const int p  = oy * W2 + ox;
    const int HW = H2 * W2;
    const float* bb = b_all + e * 5;
    out[b * HW + p]                     = acc[0] + bb[0];
    out[B * HW + (b * 2 + 0) * HW + p]  = acc[1] + bb[1];
    out[B * HW + (b * 2 + 1) * HW + p]  = acc[2] + bb[2];
    out[3 * B * HW + (b * 2 + 0) * HW + p] = acc[3] + bb[3];
    out[3 * B * HW + (b * 2 + 1) * HW + p] = acc[4] + bb[4];
}

// ---------------------------------------------------------------------------
// Launch
// ---------------------------------------------------------------------------
extern "C" void kernel_launch(void* const* d_in, const int* in_sizes, int n_in,
                              void* d_out, int out_size)
{
    const float* x        = (const float*)d_in[0];
    const float* g_conv_w = (const float*)d_in[1];
    const float* g_gamma  = (const float*)d_in[2];
    const float* g_beta   = (const float*)d_in[3];
    const float* g_mean   = (const float*)d_in[4];
    const float* g_var    = (const float*)d_in[5];
    const float* g_fc_w   = (const float*)d_in[6];
    const float* g_fc_b   = (const float*)d_in[7];
    const float* e_conv1  = (const float*)d_in[8];
    const float* e_conv2  = (const float*)d_in[9];
    const float* e_hw1    = (const float*)d_in[10];
    const float* e_hb1    = (const float*)d_in[11];
    const float* e_hw2    = (const float*)d_in[12];
    const float* e_hb2    = (const float*)d_in[13];
    float* out = (float*)d_out;

    float* ebuf1p; cudaGetSymbolAddress((void**)&ebuf1p, d_ebuf1p);
    float* ebuf2p; cudaGetSymbolAddress((void**)&ebuf2p, d_ebuf2p);

    // 0. Pad input; re-assert activation halos are zero (idempotent, cheap)
    fill_xpad_kernel<<<B * CIN * XP, 256>>>(x);
    zero_border_kernel<E1P, 1, 256><<<dim3(32, B * C1), 256>>>(ebuf1p);
    zero_border_kernel<E2P, 1, 128><<<dim3(8,  B * C2), 256>>>(ebuf2p);

    // 1. Gating conv (7x7 s2) + BN + ReLU
    conv7x7_kernel<true><<<dim3(256, 4, B), 128>>>(g_conv_w, g_gamma, g_beta, g_mean, g_var);
    // 2. Maxpool + global average
    pool_mean_kernel<<<B * C1, 256>>>();
    // 3. Logits, top-1 expert selection, aux loss
    gate_finalize_kernel<<<1, 32>>>(g_fc_w, g_fc_b, out + (out_size - 1));
    // 4. Selected expert conv1 (7x7 s2) + ReLU -> padded
    conv7x7_kernel<false><<<dim3(256, 4, B), 128>>>(e_conv1, nullptr, nullptr, nullptr, nullptr);
    // 5. Expert conv2 (3x3 s2) + ReLU -> padded
    conv2_kernel<<<dim3(64, 8, B), 128>>>(e_conv2);
    // 6. Head conv1 (3x3 s1) + bias + ReLU
    head1_kernel<<<dim3(32, 16, B), 128>>>(e_hw1, e_hb1);
    // 7. Head conv2 (1x1) + bias, scattered to (hm, wh, reg)
    head2_kernel<<<dim3(128, B), 128>>>(e_hw2, e_hb2, out);
}

// round 5
// speedup vs baseline: 2.1864x; 1.1890x over previous
#include <cuda_runtime.h>
#include <cuda_bf16.h>
#include <math.h>

// ---------------------------------------------------------------------------
// Problem constants
// ---------------------------------------------------------------------------
#define B        8
#define CIN      15          // 3*5 after reshape
#define C1       64
#define H0       512
#define W0       512
#define H1       256
#define W1       256
#define C2       128
#define H2       128
#define W2       128
#define NE       3
#define CONV1_K  (CIN*7*7)   // 735
#define CONV2_K  (C1*3*3)    // 576
#define HEAD1_K  (C2*3*3)    // 1152

// Deinterleaved padded input: per row [even 260 | odd 260] floats, 520 rows.
//  even plane: pos = 1 + e,  e = ix/2      (ix even), pads zero
//  odd  plane: pos = 2 + o,  o = (ix-1)/2  (ix odd),  pads zero
#define XW  520
#define XR  520
// ebuf1 (conv1 out, 256x256) deinterleaved for stride-2 conv2:
//  row = iy+1 (258 rows), row layout [even 128 | odd 132] = 260 floats
//  even: pos = e (e = c/2, c even);  odd: pos = 128 + 1 + o (o=(c-1)/2)
#define E1R 258
#define E1W 260
// ebuf2 (conv2 out, 128x128) padded plain: row = iy+1 (130 rows), width 132,
// interior cols pos 1..128
#define E2R 130
#define E2W 132

// ---------------------------------------------------------------------------
// Device scratch
// ---------------------------------------------------------------------------
__device__ __align__(16) float d_xpad  [(long)B*CIN*XR*XW];   // 130 MB
__device__ __align__(16) float d_gbuf  [(long)B*C1*H1*W1];    // 134 MB
__device__ __align__(16) float d_ebuf1p[(long)B*C1*E1R*E1W];  // 137 MB
__device__ __align__(16) float d_ebuf2p[(long)B*C2*E2R*E2W];  //  70 MB
__device__ __align__(16) float d_ebuf3 [(long)B*C2*H2*W2];    //  67 MB
__device__ float d_pooled[B*C1];
__device__ int   d_eidx[B];

// ---------------------------------------------------------------------------
// Packed f32x2 helpers
// ---------------------------------------------------------------------------
__device__ __forceinline__ unsigned long long pack2(float v) {
    unsigned long long r;
    asm("mov.b64 %0, {%1, %1};" : "=l"(r) : "f"(v));
    return r;
}
__device__ __forceinline__ void ffma2(unsigned long long& d,
                                      unsigned long long a,
                                      unsigned long long b) {
    asm("fma.rn.f32x2 %0, %1, %2, %0;" : "+l"(d) : "l"(a), "l"(b));
}
__device__ __forceinline__ float f2lo(unsigned long long v) {
    return __uint_as_float((unsigned int)v);
}
__device__ __forceinline__ float f2hi(unsigned long long v) {
    return __uint_as_float((unsigned int)(v >> 32));
}

// 16-oc packed FMA: 8 FFMA2 against 4 u64-pairs of weights
#define FFMA2_16(accp, vv, wA, wB, wC, wD) do {                       \
    ffma2((accp)[0], (vv), (wA).x); ffma2((accp)[1], (vv), (wA).y);   \
    ffma2((accp)[2], (vv), (wB).x); ffma2((accp)[3], (vv), (wB).y);   \
    ffma2((accp)[4], (vv), (wC).x); ffma2((accp)[5], (vv), (wC).y);   \
    ffma2((accp)[6], (vv), (wD).x); ffma2((accp)[7], (vv), (wD).y);   \
} while (0)

// ---------------------------------------------------------------------------
// Kernel 0: build deinterleaved padded input
// ---------------------------------------------------------------------------
__global__ void __launch_bounds__(256)
fill_xpad_kernel(const float* __restrict__ x)
{
    const int row = blockIdx.x;                 // 0 .. B*CIN*XR-1
    const int bc  = row / XR;
    const int r   = row - bc * XR;
    const int iy  = r - 3;
    float* dst = d_xpad + (long)row * XW;
    const float* src = x + (long)bc * (H0 * W0) + (long)iy * W0;
    const bool rowok = (unsigned)iy < (unsigned)H0;
    for (int c = threadIdx.x; c < XW; c += 256) {
        float v = 0.f;
        if (rowok) {
            if (c < 260) {                      // even plane: e = c-1, ix = 2e
                const int e = c - 1;
                if ((unsigned)e < 256u) v = src[2 * e];
            } else {                            // odd plane: o = c-262, ix = 2o+1
                const int o = c - 262;
                if ((unsigned)o < 256u) v = src[2 * o + 1];
            }
        }
        dst[c] = v;
    }
}

// ---------------------------------------------------------------------------
// Halo-zero kernels (run every launch; interiors overwritten by conv kernels)
// ---------------------------------------------------------------------------
__global__ void __launch_bounds__(256) zero_halo_e1()
{
    float* p = d_ebuf1p + (long)blockIdx.x * (E1R * E1W);
    const int t = threadIdx.x;
    for (int i = t; i < E1W; i += 256) p[i] = 0.f;          // row 0 (iy=-1)
    if (t < 256) {                                          // rows 1..256
        float* r = p + (t + 1) * E1W;
        r[128] = 0.f;                                       // odd o=-1
        r[257] = 0.f; r[258] = 0.f; r[259] = 0.f;           // odd right pads
    }
}
__global__ void __launch_bounds__(256) zero_halo_e2()
{
    float* p = d_ebuf2p + (long)blockIdx.x * (E2R * E2W);
    const int t = threadIdx.x;
    for (int i = t; i < E2W; i += 256) {
        p[i] = 0.f;                                         // row 0
        p[129 * E2W + i] = 0.f;                             // row 129
    }
    if (t < 128) {                                          // rows 1..128
        float* r = p + (t + 1) * E2W;
        r[0] = 0.f; r[129] = 0.f; r[130] = 0.f; r[131] = 0.f;
    }
}

// ---------------------------------------------------------------------------
// Kernel 1: 7x7 s2 conv, 15 -> 64, from deinterleaved padded input.
// Block 128 thr = 2 output rows x 64 lanes; lane computes 4 px, 16 oc.
// Grid (128, 4, 8).
// ---------------------------------------------------------------------------
template <bool GATING>
__global__ void __launch_bounds__(128)
conv7x7_kernel(const float* __restrict__ w_all,
               const float* __restrict__ bn_gamma,
               const float* __restrict__ bn_beta,
               const float* __restrict__ bn_mean,
               const float* __restrict__ bn_var)
{
    const int oy  = blockIdx.x * 2 + (threadIdx.x >> 6);   // 0..255
    const int ocg = blockIdx.y;                            // 0..3
    const int b   = blockIdx.z;
    const int l   = threadIdx.x & 63;                      // px0 = 4*l

    const float* w = w_all + (long)ocg * 16 * CONV1_K;
    if (!GATING) w += (long)d_eidx[b] * (C1 * CONV1_K);

    __shared__ __align__(16) float wsm[CONV1_K][16];       // 47040 B
    for (int idx = threadIdx.x; idx < 16 * CONV1_K; idx += 128) {
        const int o = idx / CONV1_K;
        const int k = idx - o * CONV1_K;
        wsm[k][o] = w[idx];
    }
    __syncthreads();

    unsigned long long acc[4][8];
#pragma unroll
    for (int p = 0; p < 4; p++)
#pragma unroll
        for (int j = 0; j < 8; j++) acc[p][j] = 0ull;

    const float* xb = d_xpad + (long)b * CIN * (XR * XW);
#pragma unroll 1
    for (int ic = 0; ic < CIN; ic++) {
#pragma unroll 1
        for (int ky = 0; ky < 7; ky++) {
            const float* row = xb + ((long)ic * XR + (2 * oy + ky)) * XW;
            const float4 e0 = *(const float4*)(row + 4 * l);
            const float4 e1 = *(const float4*)(row + 4 * l + 4);
            const float4 q0 = *(const float4*)(row + 260 + 4 * l);
            const float4 q1 = *(const float4*)(row + 260 + 4 * l + 4);
            const float E[8] = {e0.x, e0.y, e0.z, e0.w, e1.x, e1.y, e1.z, e1.w};
            const float O[8] = {q0.x, q0.y, q0.z, q0.w, q1.x, q1.y, q1.z, q1.w};
            const int kb = (ic * 7 + ky) * 7;
#pragma unroll
            for (int kx = 0; kx < 7; kx++) {
                const ulonglong2* wp = (const ulonglong2*)wsm[kb + kx];
                const ulonglong2 wA = wp[0], wB = wp[1], wC = wp[2], wD = wp[3];
#pragma unroll
                for (int p = 0; p < 4; p++) {
                    // kx odd -> even plane E[p+(kx-1)/2]; kx even -> odd O[p+kx/2]
                    const float v = (kx & 1) ? E[p + ((kx - 1) >> 1)]
                                             : O[p + (kx >> 1)];
                    const unsigned long long vv = pack2(v);
                    FFMA2_16(acc[p], vv, wA, wB, wC, wD);
                }
            }
        }
    }

    if (GATING) {
#pragma unroll
        for (int j = 0; j < 8; j++) {
            const int oca = ocg * 16 + 2 * j;
            const int ocb = oca + 1;
            const float sa = bn_gamma[oca] * rsqrtf(bn_var[oca] + 1e-5f);
            const float sb = bn_gamma[ocb] * rsqrtf(bn_var[ocb] + 1e-5f);
            const float ta = bn_beta[oca] - bn_mean[oca] * sa;
            const float tb = bn_beta[ocb] - bn_mean[ocb] * sb;
            float4 va, vb;
            va.x = fmaxf(f2lo(acc[0][j]) * sa + ta, 0.f);
            va.y = fmaxf(f2lo(acc[1][j]) * sa + ta, 0.f);
            va.z = fmaxf(f2lo(acc[2][j]) * sa + ta, 0.f);
            va.w = fmaxf(f2lo(acc[3][j]) * sa + ta, 0.f);
            vb.x = fmaxf(f2hi(acc[0][j]) * sb + tb, 0.f);
            vb.y = fmaxf(f2hi(acc[1][j]) * sb + tb, 0.f);
            vb.z = fmaxf(f2hi(acc[2][j]) * sb + tb, 0.f);
            vb.w = fmaxf(f2hi(acc[3][j]) * sb + tb, 0.f);
            *(float4*)(d_gbuf + ((long)(b * C1 + oca) * H1 + oy) * W1 + 4 * l) = va;
            *(float4*)(d_gbuf + ((long)(b * C1 + ocb) * H1 + oy) * W1 + 4 * l) = vb;
        }
    } else {
        // write deinterleaved into ebuf1p: even px -> even plane, odd -> odd
#pragma unroll
        for (int j = 0; j < 8; j++) {
            const int oca = ocg * 16 + 2 * j;
            const int ocb = oca + 1;
            const float fa0 = fmaxf(f2lo(acc[0][j]), 0.f);
            const float fa1 = fmaxf(f2lo(acc[1][j]), 0.f);
            const float fa2 = fmaxf(f2lo(acc[2][j]), 0.f);
            const float fa3 = fmaxf(f2lo(acc[3][j]), 0.f);
            const float fb0 = fmaxf(f2hi(acc[0][j]), 0.f);
            const float fb1 = fmaxf(f2hi(acc[1][j]), 0.f);
            const float fb2 = fmaxf(f2hi(acc[2][j]), 0.f);
            const float fb3 = fmaxf(f2hi(acc[3][j]), 0.f);
            float* ra = d_ebuf1p + ((long)(b * C1 + oca) * E1R + (oy + 1)) * E1W;
            float* rb = d_ebuf1p + ((long)(b * C1 + ocb) * E1R + (oy + 1)) * E1W;
            // even: px 4l,4l+2 -> pos 2l,2l+1 ; odd: px 4l+1,4l+3 -> pos 129+2l,130+2l
            *(float2*)(ra + 2 * l) = make_float2(fa0, fa2);
            ra[129 + 2 * l] = fa1;  ra[130 + 2 * l] = fa3;
            *(float2*)(rb + 2 * l) = make_float2(fb0, fb2);
            rb[129 + 2 * l] = fb1;  rb[130 + 2 * l] = fb3;
        }
    }
}

// ---------------------------------------------------------------------------
// Kernel 2: maxpool 3x3 s2 pad1 (256^2 -> 128^2) + spatial mean, per (b,c).
// ---------------------------------------------------------------------------
__global__ void pool_mean_kernel()
{
    const int bc = blockIdx.x;
    const float* p = d_gbuf + (long)bc * (H1 * W1);
    float sum = 0.f;
    for (int i = threadIdx.x; i < H2 * W2; i += blockDim.x) {
        const int py = i >> 7, px = i & 127;
        float m = -1e30f;
#pragma unroll
        for (int dy = 0; dy < 3; dy++) {
            const int iy = py * 2 - 1 + dy;
            if ((unsigned)iy >= (unsigned)H1) continue;
            const float* row = p + iy * W1;
#pragma unroll
            for (int dx = 0; dx < 3; dx++) {
                const int ix = px * 2 - 1 + dx;
                if ((unsigned)ix < (unsigned)W1) m = fmaxf(m, row[ix]);
            }
        }
        sum += m;
    }
    __shared__ float red[256];
    red[threadIdx.x] = sum;
    __syncthreads();
    for (int s = 128; s > 0; s >>= 1) {
        if (threadIdx.x < s) red[threadIdx.x] += red[threadIdx.x + s];
        __syncthreads();
    }
    if (threadIdx.x == 0) d_pooled[bc] = red[0] * (1.f / (H2 * W2));
}

// ---------------------------------------------------------------------------
// Kernel 3: FC -> logits -> top-1 expert + aux loss.
// ---------------------------------------------------------------------------
__global__ void gate_finalize_kernel(const float* __restrict__ fcw,
                                     const float* __restrict__ fcb,
                                     float* __restrict__ out_loss)
{
    __shared__ float logits[B][NE];
    const int t = threadIdx.x;
    if (t < B * NE) {
        const int b = t / NE, e = t % NE;
        float s = fcb[e];
        const float* pw = fcw + e * C1;
        const float* pp = d_pooled + b * C1;
        for (int i = 0; i < C1; i++) s += pp[i] * pw[i];
        logits[b][e] = s;
    }
    __syncthreads();
    if (t == 0) {
        float dens[NE]  = {0.f, 0.f, 0.f};
        float proxy[NE] = {0.f, 0.f, 0.f};
        for (int b = 0; b < B; b++) {
            int bi = 0;
            for (int e = 1; e < NE; e++)
                if (logits[b][e] > logits[b][bi]) bi = e;
            d_eidx[b] = bi;
            dens[bi] += 1.f / B;
            float mx = logits[b][0];
            for (int e = 1; e < NE; e++) mx = fmaxf(mx, logits[b][e]);
            float ex[NE], sum = 0.f;
            for (int e = 0; e < NE; e++) { ex[e] = expf(logits[b][e] - mx); sum += ex[e]; }
            for (int e = 0; e < NE; e++) proxy[e] += ex[e] / sum * (1.f / B);
        }
        float aux = 0.f;
        for (int e = 0; e < NE; e++) aux += dens[e] * proxy[e];
        *out_loss = 0.01f * aux * (float)NE;
    }
}

// ---------------------------------------------------------------------------
// Kernel 4: 3x3 s2 conv, 64 -> 128, deinterleaved input -> padded ebuf2.
// Block 128 thr = 4 output rows x 32 lanes; lane computes 4 px, 16 oc.
// Grid (32, 8, 8).
// ---------------------------------------------------------------------------
__global__ void __launch_bounds__(128)
conv2_kernel(const float* __restrict__ w_all)
{
    const int oy  = blockIdx.x * 4 + (threadIdx.x >> 5);  // 0..127
    const int ocg = blockIdx.y;                           // 0..7
    const int b   = blockIdx.z;
    const int l   = threadIdx.x & 31;                     // px0 = 4*l

    const float* w = w_all + ((long)d_eidx[b] * C2 + ocg * 16) * CONV2_K;
    __shared__ __align__(16) float wsm[CONV2_K][16];      // 36864 B
    for (int idx = threadIdx.x; idx < 16 * CONV2_K; idx += 128) {
        const int o = idx / CONV2_K;
        const int k = idx - o * CONV2_K;
        wsm[k][o] = w[idx];
    }
    __syncthreads();

    unsigned long long acc[4][8];
#pragma unroll
    for (int p = 0; p < 4; p++)
#pragma unroll
        for (int j = 0; j < 8; j++) acc[p][j] = 0ull;

    const float* ib = d_ebuf1p + (long)b * C1 * (E1R * E1W);
#pragma unroll 1
    for (int ic = 0; ic < C1; ic++) {
        const float* xc = ib + (long)ic * (E1R * E1W);
#pragma unroll
        for (int ky = 0; ky < 3; ky++) {
            const float* row = xc + (2 * oy + ky) * E1W;
            const float4 ev = *(const float4*)(row + 4 * l);
            const float4 q0 = *(const float4*)(row + 128 + 4 * l);
            const float4 q1 = *(const float4*)(row + 128 + 4 * l + 4);
            const float E[4] = {ev.x, ev.y, ev.z, ev.w};
            const float O[8] = {q0.x, q0.y, q0.z, q0.w, q1.x, q1.y, q1.z, q1.w};
            const int kb = (ic * 3 + ky) * 3;
#pragma unroll
            for (int kx = 0; kx < 3; kx++) {
                const ulonglong2* wp = (const ulonglong2*)wsm[kb + kx];
                const ulonglong2 wA = wp[0], wB = wp[1], wC = wp[2], wD = wp[3];
#pragma unroll
                for (int p = 0; p < 4; p++) {
                    // kx=0 -> O[p]; kx=1 -> E[p]; kx=2 -> O[p+1]
                    const float v = (kx == 1) ? E[p] : ((kx == 0) ? O[p] : O[p + 1]);
                    const unsigned long long vv = pack2(v);
                    FFMA2_16(acc[p], vv, wA, wB, wC, wD);
                }
            }
        }
    }

#pragma unroll
    for (int j = 0; j < 8; j++) {
        const int oca = ocg * 16 + 2 * j;
        const int ocb = oca + 1;
        float* ra = d_ebuf2p + ((long)(b * C2 + oca) * E2R + (oy + 1)) * E2W + 1 + 4 * l;
        float* rb = d_ebuf2p + ((long)(b * C2 + ocb) * E2R + (oy + 1)) * E2W + 1 + 4 * l;
        ra[0] = fmaxf(f2lo(acc[0][j]), 0.f);
        ra[1] = fmaxf(f2lo(acc[1][j]), 0.f);
        ra[2] = fmaxf(f2lo(acc[2][j]), 0.f);
        ra[3] = fmaxf(f2lo(acc[3][j]), 0.f);
        rb[0] = fmaxf(f2hi(acc[0][j]), 0.f);
        rb[1] = fmaxf(f2hi(acc[1][j]), 0.f);
        rb[2] = fmaxf(f2hi(acc[2][j]), 0.f);
        rb[3] = fmaxf(f2hi(acc[3][j]), 0.f);
    }
}

// ---------------------------------------------------------------------------
// Kernel 5: 3x3 s1 conv, 128 -> 128, + bias, ReLU.  Padded input ebuf2.
// Block 128 thr = 4 output rows x 32 lanes; lane computes 4 px, 16 oc.
// Weights in 72KB dynamic smem.  Grid (32, 8, 8).
// ---------------------------------------------------------------------------
__global__ void __launch_bounds__(128)
head1_kernel(const float* __restrict__ w_all,
             const float* __restrict__ b_all)
{
    extern __shared__ __align__(16) float wsm[];          // HEAD1_K * 16 floats
    const int oy  = blockIdx.x * 4 + (threadIdx.x >> 5);  // 0..127
    const int ocg = blockIdx.y;                           // 0..7
    const int b   = blockIdx.z;
    const int l   = threadIdx.x & 31;                     // px0 = 4*l
    const int e   = d_eidx[b];

    const float* w = w_all + ((long)e * C2 + ocg * 16) * HEAD1_K;
    for (int idx = threadIdx.x; idx < 16 * HEAD1_K; idx += 128) {
        const int o = idx / HEAD1_K;
        const int k = idx - o * HEAD1_K;
        wsm[k * 16 + o] = w[idx];
    }
    __syncthreads();

    unsigned long long acc[4][8];
#pragma unroll
    for (int p = 0; p < 4; p++)
#pragma unroll
        for (int j = 0; j < 8; j++) acc[p][j] = 0ull;

    const float* ib = d_ebuf2p + (long)b * C2 * (E2R * E2W);
#pragma unroll 1
    for (int ic = 0; ic < C2; ic++) {
        const float* xc = ib + (long)ic * (E2R * E2W);
        float W3[3][8];
#pragma unroll
        for (int r = 0; r < 3; r++) {
            const float4 a = *(const float4*)(xc + (oy + r) * E2W + 4 * l);
            const float4 c = *(const float4*)(xc + (oy + r) * E2W + 4 * l + 4);
            W3[r][0] = a.x; W3[r][1] = a.y; W3[r][2] = a.z; W3[r][3] = a.w;
            W3[r][4] = c.x; W3[r][5] = c.y; W3[r][6] = c.z; W3[r][7] = c.w;
        }
#pragma unroll
        for (int ky = 0; ky < 3; ky++) {
            const int kb = (ic * 3 + ky) * 3;
#pragma unroll
            for (int kx = 0; kx < 3; kx++) {
                const ulonglong2* wp = (const ulonglong2*)(wsm + (kb + kx) * 16);
                const ulonglong2 wA = wp[0], wB = wp[1], wC = wp[2], wD = wp[3];
#pragma unroll
                for (int p = 0; p < 4; p++) {
                    const unsigned long long vv = pack2(W3[ky][p + kx]);
                    FFMA2_16(acc[p], vv, wA, wB, wC, wD);
                }
            }
        }
    }

#pragma unroll
    for (int j = 0; j < 8; j++) {
        const int oca = ocg * 16 + 2 * j;
        const int ocb = oca + 1;
        const float ba = b_all[e * C2 + oca];
        const float bb = b_all[e * C2 + ocb];
        float4 va, vb;
        va.x = fmaxf(f2lo(acc[0][j]) + ba, 0.f);
        va.y = fmaxf(f2lo(acc[1][j]) + ba, 0.f);
        va.z = fmaxf(f2lo(acc[2][j]) + ba, 0.f);
        va.w = fmaxf(f2lo(acc[3][j]) + ba, 0.f);
        vb.x = fmaxf(f2hi(acc[0][j]) + bb, 0.f);
        vb.y = fmaxf(f2hi(acc[1][j]) + bb, 0.f);
        vb.z = fmaxf(f2hi(acc[2][j]) + bb, 0.f);
        vb.w = fmaxf(f2hi(acc[3][j]) + bb, 0.f);
        *(float4*)(d_ebuf3 + ((long)(b * C2 + oca) * H2 + oy) * W2 + 4 * l) = va;
        *(float4*)(d_ebuf3 + ((long)(b * C2 + ocb) * H2 + oy) * W2 + 4 * l) = vb;
    }
}

// ---------------------------------------------------------------------------
// Kernel 6: 1x1 conv 128 -> 5 + bias, scatter into (hm, wh, reg) layout.
// ---------------------------------------------------------------------------
__global__ void __launch_bounds__(128)
head2_kernel(const float* __restrict__ w_all,
             const float* __restrict__ b_all,
             float* __restrict__ out)
{
    const int oy = blockIdx.x;
    const int b  = blockIdx.y;
    const int ox = threadIdx.x;
    const int e  = d_eidx[b];

    __shared__ __align__(16) float ws[C2][8];
    for (int idx = threadIdx.x; idx < 5 * C2; idx += 128) {
        const int j = idx / C2, ic = idx - j * C2;
        ws[ic][j] = w_all[(long)e * 5 * C2 + idx];
    }
    __syncthreads();

    float acc[5] = {0.f, 0.f, 0.f, 0.f, 0.f};
    const float* ib = d_ebuf3 + (long)b * C2 * H2 * W2 + oy * W2 + ox;
    for (int ic = 0; ic < C2; ic++) {
        const float v = __ldg(ib + ic * (H2 * W2));
        const float4 w4 = *(const float4*)ws[ic];
        acc[0] += v * w4.x;
        acc[1] += v * w4.y;
        acc[2] += v * w4.z;
        acc[3] += v * w4.w;
        acc[4] += v * ws[ic][4];
    }

    const int p  = oy * W2 + ox;
    const int HW = H2 * W2;
    const float* bb = b_all + e * 5;
    out[b * HW + p]                        = acc[0] + bb[0];
    out[B * HW + (b * 2 + 0) * HW + p]     = acc[1] + bb[1];
    out[B * HW + (b * 2 + 1) * HW + p]     = acc[2] + bb[2];
    out[3 * B * HW + (b * 2 + 0) * HW + p] = acc[3] + bb[3];
    out[3 * B * HW + (b * 2 + 1) * HW + p] = acc[4] + bb[4];
}

// ---------------------------------------------------------------------------
// Launch
// ---------------------------------------------------------------------------
extern "C" void kernel_launch(void* const* d_in, const int* in_sizes, int n_in,
                              void* d_out, int out_size)
{
    const float* x        = (const float*)d_in[0];
    const float* g_conv_w = (const float*)d_in[1];
    const float* g_gamma  = (const float*)d_in[2];
    const float* g_beta   = (const float*)d_in[3];
    const float* g_mean   = (const float*)d_in[4];
    const float* g_var    = (const float*)d_in[5];
    const float* g_fc_w   = (const float*)d_in[6];
    const float* g_fc_b   = (const float*)d_in[7];
    const float* e_conv1  = (const float*)d_in[8];
    const float* e_conv2  = (const float*)d_in[9];
    const float* e_hw1    = (const float*)d_in[10];
    const float* e_hb1    = (const float*)d_in[11];
    const float* e_hw2    = (const float*)d_in[12];
    const float* e_hb2    = (const float*)d_in[13];
    float* out = (float*)d_out;

    // head1 uses 72KB dynamic smem (above the 48KB static limit)
    cudaFuncSetAttribute(head1_kernel,
                         cudaFuncAttributeMaxDynamicSharedMemorySize,
                         16 * HEAD1_K * (int)sizeof(float));

    // 0. Deinterleaved padded input + activation halos
    fill_xpad_kernel<<<B * CIN * XR, 256>>>(x);
    zero_halo_e1<<<B * C1, 256>>>();
    zero_halo_e2<<<B * C2, 256>>>();

    // 1. Gating conv (7x7 s2) + BN + ReLU -> gbuf (plain)
    conv7x7_kernel<true><<<dim3(128, 4, B), 128>>>(g_conv_w, g_gamma, g_beta, g_mean, g_var);
    // 2. Maxpool + global average
    pool_mean_kernel<<<B * C1, 256>>>();
    // 3. Logits, top-1 expert selection, aux loss
    gate_finalize_kernel<<<1, 32>>>(g_fc_w, g_fc_b, out + (out_size - 1));
    // 4. Selected expert conv1 (7x7 s2) + ReLU -> ebuf1p (deinterleaved)
    conv7x7_kernel<false><<<dim3(128, 4, B), 128>>>(e_conv1, nullptr, nullptr, nullptr, nullptr);
    // 5. Expert conv2 (3x3 s2) + ReLU -> ebuf2p (padded)
    conv2_kernel<<<dim3(32, 8, B), 128>>>(e_conv2);
    // 6. Head conv1 (3x3 s1) + bias + ReLU -> ebuf3
    head1_kernel<<<dim3(32, 8, B), 128, 16 * HEAD1_K * sizeof(float)>>>(e_hw1, e_hb1);
    // 7. Head conv2 (1x1) + bias, scattered to (hm, wh, reg)
    head2_kernel<<<dim3(128, B), 128>>>(e_hw2, e_hb2, out);
}

// round 7
// speedup vs baseline: 2.4126x; 1.1035x over previous
#include <cuda_runtime.h>
#include <cuda_bf16.h>
#include <math.h>

// ---------------------------------------------------------------------------
// Problem constants
// ---------------------------------------------------------------------------
#define B        8
#define CIN      15          // 3*5 after reshape
#define C1       64
#define H0       512
#define W0       512
#define H1       256
#define W1       256
#define C2       128
#define H2       128
#define W2       128
#define NE       3
#define CONV1_K  (CIN*7*7)   // 735
#define CONV2_K  (C1*3*3)    // 576
#define HEAD1_K  (C2*3*3)    // 1152
#define HEAD1_KH (64*3*3)    // 576 (one ic-half)

// Deinterleaved padded input: per row [even 260 | odd 260] floats, 520 rows.
#define XW  520
#define XR  520
// ebuf1 (conv1 out, 256x256) deinterleaved: row = iy+1 (258 rows),
// [even 128 | odd 132] = 260 floats
#define E1R 258
#define E1W 260
// ebuf2 (conv2 out, 128x128) padded plain: 130 rows x 132, interior 1..128
#define E2R 130
#define E2W 132

// ---------------------------------------------------------------------------
// Device scratch
// ---------------------------------------------------------------------------
__device__ __align__(16) float d_xpad  [(long)B*CIN*XR*XW];
__device__ __align__(16) float d_gbuf  [(long)B*C1*H1*W1];
__device__ __align__(16) float d_ebuf1p[(long)B*C1*E1R*E1W];
__device__ __align__(16) float d_ebuf2p[(long)B*C2*E2R*E2W];
__device__ __align__(16) float d_ebuf3 [(long)B*C2*H2*W2];
__device__ float d_pooled[B*C1];
__device__ int   d_eidx[B];

// ---------------------------------------------------------------------------
// Packed f32x2 helpers
// ---------------------------------------------------------------------------
__device__ __forceinline__ unsigned long long pack2(float v) {
    unsigned long long r;
    asm("mov.b64 %0, {%1, %1};" : "=l"(r) : "f"(v));
    return r;
}
__device__ __forceinline__ void ffma2(unsigned long long& d,
                                      unsigned long long a,
                                      unsigned long long b) {
    asm("fma.rn.f32x2 %0, %1, %2, %0;" : "+l"(d) : "l"(a), "l"(b));
}
__device__ __forceinline__ float f2lo(unsigned long long v) {
    return __uint_as_float((unsigned int)v);
}
__device__ __forceinline__ float f2hi(unsigned long long v) {
    return __uint_as_float((unsigned int)(v >> 32));
}

#define FFMA2_16(accp, vv, wA, wB, wC, wD) do {                       \
    ffma2((accp)[0], (vv), (wA).x); ffma2((accp)[1], (vv), (wA).y);   \
    ffma2((accp)[2], (vv), (wB).x); ffma2((accp)[3], (vv), (wB).y);   \
    ffma2((accp)[4], (vv), (wC).x); ffma2((accp)[5], (vv), (wC).y);   \
    ffma2((accp)[6], (vv), (wD).x); ffma2((accp)[7], (vv), (wD).y);   \
} while (0)

// ---------------------------------------------------------------------------
// Kernel 0: prep — pad/deinterleave input + zero activation halos (one launch)
//   blocks [0, B*CIN*XR)                     : xpad rows
//   blocks [B*CIN*XR, +B*C1)                 : ebuf1p halos
//   blocks [B*CIN*XR+B*C1, +B*C2)            : ebuf2p halos
// ---------------------------------------------------------------------------
#define PREP_X   (B*CIN*XR)
#define PREP_E1  (PREP_X + B*C1)
#define PREP_E2  (PREP_E1 + B*C2)

__global__ void __launch_bounds__(256)
prep_kernel(const float* __restrict__ x)
{
    const int blk = blockIdx.x;
    const int t   = threadIdx.x;
    if (blk < PREP_X) {
        const int bc = blk / XR;
        const int r  = blk - bc * XR;
        const int iy = r - 3;
        float* dst = d_xpad + (long)blk * XW;
        const float* src = x + (long)bc * (H0 * W0) + (long)iy * W0;
        const bool rowok = (unsigned)iy < (unsigned)H0;
        for (int c = t; c < XW; c += 256) {
            float v = 0.f;
            if (rowok) {
                if (c < 260) {
                    const int e = c - 1;
                    if ((unsigned)e < 256u) v = src[2 * e];
                } else {
                    const int o = c - 262;
                    if ((unsigned)o < 256u) v = src[2 * o + 1];
                }
            }
            dst[c] = v;
        }
    } else if (blk < PREP_E1) {
        float* p = d_ebuf1p + (long)(blk - PREP_X) * (E1R * E1W);
        for (int i = t; i < E1W; i += 256) p[i] = 0.f;      // row 0
        {
            float* r = p + (t + 1) * E1W;                   // rows 1..256
            r[128] = 0.f;
            r[257] = 0.f; r[258] = 0.f; r[259] = 0.f;
        }
    } else {
        float* p = d_ebuf2p + (long)(blk - PREP_E1) * (E2R * E2W);
        for (int i = t; i < E2W; i += 256) {
            p[i] = 0.f;                                     // row 0
            p[129 * E2W + i] = 0.f;                         // row 129
        }
        if (t < 128) {
            float* r = p + (t + 1) * E2W;                   // rows 1..128
            r[0] = 0.f; r[129] = 0.f; r[130] = 0.f; r[131] = 0.f;
        }
    }
}

// ---------------------------------------------------------------------------
// Kernel 1: 7x7 s2 conv, 15 -> 64, deinterleaved padded input.
// Block 128 thr = 2 output rows x 64 lanes; lane computes 4 px, 16 oc.
// Grid (128, 4, 8).
// ---------------------------------------------------------------------------
template <bool GATING>
__global__ void __launch_bounds__(128, 4)
conv7x7_kernel(const float* __restrict__ w_all,
               const float* __restrict__ bn_gamma,
               const float* __restrict__ bn_beta,
               const float* __restrict__ bn_mean,
               const float* __restrict__ bn_var)
{
    const int oy  = blockIdx.x * 2 + (threadIdx.x >> 6);
    const int ocg = blockIdx.y;
    const int b   = blockIdx.z;
    const int l   = threadIdx.x & 63;

    const float* w = w_all + (long)ocg * 16 * CONV1_K;
    if (!GATING) w += (long)d_eidx[b] * (C1 * CONV1_K);

    __shared__ __align__(16) float wsm[CONV1_K][16];
    for (int idx = threadIdx.x; idx < 16 * CONV1_K; idx += 128) {
        const int o = idx / CONV1_K;
        const int k = idx - o * CONV1_K;
        wsm[k][o] = w[idx];
    }
    __syncthreads();

    unsigned long long acc[4][8];
#pragma unroll
    for (int p = 0; p < 4; p++)
#pragma unroll
        for (int j = 0; j < 8; j++) acc[p][j] = 0ull;

    const float* xb = d_xpad + (long)b * CIN * (XR * XW);
#pragma unroll 1
    for (int ic = 0; ic < CIN; ic++) {
#pragma unroll
        for (int ky = 0; ky < 7; ky++) {
            const float* row = xb + ((long)ic * XR + (2 * oy + ky)) * XW;
            const float4 e0 = *(const float4*)(row + 4 * l);
            const float4 e1 = *(const float4*)(row + 4 * l + 4);
            const float4 q0 = *(const float4*)(row + 260 + 4 * l);
            const float4 q1 = *(const float4*)(row + 260 + 4 * l + 4);
            const float E[8] = {e0.x, e0.y, e0.z, e0.w, e1.x, e1.y, e1.z, e1.w};
            const float O[8] = {q0.x, q0.y, q0.z, q0.w, q1.x, q1.y, q1.z, q1.w};
            const int kb = (ic * 7 + ky) * 7;
#pragma unroll
            for (int kx = 0; kx < 7; kx++) {
                const ulonglong2* wp = (const ulonglong2*)wsm[kb + kx];
                const ulonglong2 wA = wp[0], wB = wp[1], wC = wp[2], wD = wp[3];
#pragma unroll
                for (int p = 0; p < 4; p++) {
                    const float v = (kx & 1) ? E[p + ((kx - 1) >> 1)]
                                             : O[p + (kx >> 1)];
                    const unsigned long long vv = pack2(v);
                    FFMA2_16(acc[p], vv, wA, wB, wC, wD);
                }
            }
        }
    }

    if (GATING) {
#pragma unroll
        for (int j = 0; j < 8; j++) {
            const int oca = ocg * 16 + 2 * j;
            const int ocb = oca + 1;
            const float sa = bn_gamma[oca] * rsqrtf(bn_var[oca] + 1e-5f);
            const float sb = bn_gamma[ocb] * rsqrtf(bn_var[ocb] + 1e-5f);
            const float ta = bn_beta[oca] - bn_mean[oca] * sa;
            const float tb = bn_beta[ocb] - bn_mean[ocb] * sb;
            float4 va, vb;
            va.x = fmaxf(f2lo(acc[0][j]) * sa + ta, 0.f);
            va.y = fmaxf(f2lo(acc[1][j]) * sa + ta, 0.f);
            va.z = fmaxf(f2lo(acc[2][j]) * sa + ta, 0.f);
            va.w = fmaxf(f2lo(acc[3][j]) * sa + ta, 0.f);
            vb.x = fmaxf(f2hi(acc[0][j]) * sb + tb, 0.f);
            vb.y = fmaxf(f2hi(acc[1][j]) * sb + tb, 0.f);
            vb.z = fmaxf(f2hi(acc[2][j]) * sb + tb, 0.f);
            vb.w = fmaxf(f2hi(acc[3][j]) * sb + tb, 0.f);
            *(float4*)(d_gbuf + ((long)(b * C1 + oca) * H1 + oy) * W1 + 4 * l) = va;
            *(float4*)(d_gbuf + ((long)(b * C1 + ocb) * H1 + oy) * W1 + 4 * l) = vb;
        }
    } else {
#pragma unroll
        for (int j = 0; j < 8; j++) {
            const int oca = ocg * 16 + 2 * j;
            const int ocb = oca + 1;
            const float fa0 = fmaxf(f2lo(acc[0][j]), 0.f);
            const float fa1 = fmaxf(f2lo(acc[1][j]), 0.f);
            const float fa2 = fmaxf(f2lo(acc[2][j]), 0.f);
            const float fa3 = fmaxf(f2lo(acc[3][j]), 0.f);
            const float fb0 = fmaxf(f2hi(acc[0][j]), 0.f);
            const float fb1 = fmaxf(f2hi(acc[1][j]), 0.f);
            const float fb2 = fmaxf(f2hi(acc[2][j]), 0.f);
            const float fb3 = fmaxf(f2hi(acc[3][j]), 0.f);
            float* ra = d_ebuf1p + ((long)(b * C1 + oca) * E1R + (oy + 1)) * E1W;
            float* rb = d_ebuf1p + ((long)(b * C1 + ocb) * E1R + (oy + 1)) * E1W;
            *(float2*)(ra + 2 * l) = make_float2(fa0, fa2);
            ra[129 + 2 * l] = fa1;  ra[130 + 2 * l] = fa3;
            *(float2*)(rb + 2 * l) = make_float2(fb0, fb2);
            rb[129 + 2 * l] = fb1;  rb[130 + 2 * l] = fb3;
        }
    }
}

// ---------------------------------------------------------------------------
// Kernel 2: maxpool 3x3 s2 pad1 + spatial mean, per (b,c).
// ---------------------------------------------------------------------------
__global__ void pool_mean_kernel()
{
    const int bc = blockIdx.x;
    const float* p = d_gbuf + (long)bc * (H1 * W1);
    float sum = 0.f;
    for (int i = threadIdx.x; i < H2 * W2; i += blockDim.x) {
        const int py = i >> 7, px = i & 127;
        float m = -1e30f;
#pragma unroll
        for (int dy = 0; dy < 3; dy++) {
            const int iy = py * 2 - 1 + dy;
            if ((unsigned)iy >= (unsigned)H1) continue;
            const float* row = p + iy * W1;
#pragma unroll
            for (int dx = 0; dx < 3; dx++) {
                const int ix = px * 2 - 1 + dx;
                if ((unsigned)ix < (unsigned)W1) m = fmaxf(m, row[ix]);
            }
        }
        sum += m;
    }
    __shared__ float red[256];
    red[threadIdx.x] = sum;
    __syncthreads();
    for (int s = 128; s > 0; s >>= 1) {
        if (threadIdx.x < s) red[threadIdx.x] += red[threadIdx.x + s];
        __syncthreads();
    }
    if (threadIdx.x == 0) d_pooled[bc] = red[0] * (1.f / (H2 * W2));
}

// ---------------------------------------------------------------------------
// Kernel 3: FC -> logits -> top-1 expert + aux loss.
// ---------------------------------------------------------------------------
__global__ void gate_finalize_kernel(const float* __restrict__ fcw,
                                     const float* __restrict__ fcb,
                                     float* __restrict__ out_loss)
{
    __shared__ float logits[B][NE];
    const int t = threadIdx.x;
    if (t < B * NE) {
        const int b = t / NE, e = t % NE;
        float s = fcb[e];
        const float* pw = fcw + e * C1;
        const float* pp = d_pooled + b * C1;
        for (int i = 0; i < C1; i++) s += pp[i] * pw[i];
        logits[b][e] = s;
    }
    __syncthreads();
    if (t == 0) {
        float dens[NE]  = {0.f, 0.f, 0.f};
        float proxy[NE] = {0.f, 0.f, 0.f};
        for (int b = 0; b < B; b++) {
            int bi = 0;
            for (int e = 1; e < NE; e++)
                if (logits[b][e] > logits[b][bi]) bi = e;
            d_eidx[b] = bi;
            dens[bi] += 1.f / B;
            float mx = logits[b][0];
            for (int e = 1; e < NE; e++) mx = fmaxf(mx, logits[b][e]);
            float ex[NE], sum = 0.f;
            for (int e = 0; e < NE; e++) { ex[e] = expf(logits[b][e] - mx); sum += ex[e]; }
            for (int e = 0; e < NE; e++) proxy[e] += ex[e] / sum * (1.f / B);
        }
        float aux = 0.f;
        for (int e = 0; e < NE; e++) aux += dens[e] * proxy[e];
        *out_loss = 0.01f * aux * (float)NE;
    }
}

// ---------------------------------------------------------------------------
// Kernel 4: 3x3 s2 conv, 64 -> 128, deinterleaved input -> padded ebuf2.
// Block 128 thr = 4 output rows x 32 lanes; lane computes 4 px, 16 oc.
// Grid (32, 8, 8).
// ---------------------------------------------------------------------------
__global__ void __launch_bounds__(128, 4)
conv2_kernel(const float* __restrict__ w_all)
{
    const int oy  = blockIdx.x * 4 + (threadIdx.x >> 5);
    const int ocg = blockIdx.y;
    const int b   = blockIdx.z;
    const int l   = threadIdx.x & 31;

    const float* w = w_all + ((long)d_eidx[b] * C2 + ocg * 16) * CONV2_K;
    __shared__ __align__(16) float wsm[CONV2_K][16];
    for (int idx = threadIdx.x; idx < 16 * CONV2_K; idx += 128) {
        const int o = idx / CONV2_K;
        const int k = idx - o * CONV2_K;
        wsm[k][o] = w[idx];
    }
    __syncthreads();

    unsigned long long acc[4][8];
#pragma unroll
    for (int p = 0; p < 4; p++)
#pragma unroll
        for (int j = 0; j < 8; j++) acc[p][j] = 0ull;

    const float* ib = d_ebuf1p + (long)b * C1 * (E1R * E1W);
#pragma unroll 1
    for (int ic = 0; ic < C1; ic++) {
        const float* xc = ib + (long)ic * (E1R * E1W);
#pragma unroll
        for (int ky = 0; ky < 3; ky++) {
            const float* row = xc + (2 * oy + ky) * E1W;
            const float4 ev = *(const float4*)(row + 4 * l);
            const float4 q0 = *(const float4*)(row + 128 + 4 * l);
            const float4 q1 = *(const float4*)(row + 128 + 4 * l + 4);
            const float E[4] = {ev.x, ev.y, ev.z, ev.w};
            const float O[8] = {q0.x, q0.y, q0.z, q0.w, q1.x, q1.y, q1.z, q1.w};
            const int kb = (ic * 3 + ky) * 3;
#pragma unroll
            for (int kx = 0; kx < 3; kx++) {
                const ulonglong2* wp = (const ulonglong2*)wsm[kb + kx];
                const ulonglong2 wA = wp[0], wB = wp[1], wC = wp[2], wD = wp[3];
#pragma unroll
                for (int p = 0; p < 4; p++) {
                    const float v = (kx == 1) ? E[p] : ((kx == 0) ? O[p] : O[p + 1]);
                    const unsigned long long vv = pack2(v);
                    FFMA2_16(acc[p], vv, wA, wB, wC, wD);
                }
            }
        }
    }

#pragma unroll
    for (int j = 0; j < 8; j++) {
        const int oca = ocg * 16 + 2 * j;
        const int ocb = oca + 1;
        float* ra = d_ebuf2p + ((long)(b * C2 + oca) * E2R + (oy + 1)) * E2W + 1 + 4 * l;
        float* rb = d_ebuf2p + ((long)(b * C2 + ocb) * E2R + (oy + 1)) * E2W + 1 + 4 * l;
        ra[0] = fmaxf(f2lo(acc[0][j]), 0.f);
        ra[1] = fmaxf(f2lo(acc[1][j]), 0.f);
        ra[2] = fmaxf(f2lo(acc[2][j]), 0.f);
        ra[3] = fmaxf(f2lo(acc[3][j]), 0.f);
        rb[0] = fmaxf(f2hi(acc[0][j]), 0.f);
        rb[1] = fmaxf(f2hi(acc[1][j]), 0.f);
        rb[2] = fmaxf(f2hi(acc[2][j]), 0.f);
        rb[3] = fmaxf(f2hi(acc[3][j]), 0.f);
    }
}

// ---------------------------------------------------------------------------
// Kernel 5: 3x3 s1 conv, 128 -> 128, + bias, ReLU.  Padded input ebuf2.
// Block 128 thr = 4 rows x 32 lanes; lane computes 4 px, 16 oc.
// Weights staged in TWO 36KB passes over ic halves (occupancy: 4 blocks/SM).
// Grid (32, 8, 8).
// ---------------------------------------------------------------------------
__global__ void __launch_bounds__(128, 4)
head1_kernel(const float* __restrict__ w_all,
             const float* __restrict__ b_all)
{
    __shared__ __align__(16) float wsm[HEAD1_KH][16];     // 36864 B
    const int oy  = blockIdx.x * 4 + (threadIdx.x >> 5);
    const int ocg = blockIdx.y;
    const int b   = blockIdx.z;
    const int l   = threadIdx.x & 31;
    const int e   = d_eidx[b];

    const float* wbase = w_all + ((long)e * C2 + ocg * 16) * HEAD1_K;

    unsigned long long acc[4][8];
#pragma unroll
    for (int p = 0; p < 4; p++)
#pragma unroll
        for (int j = 0; j < 8; j++) acc[p][j] = 0ull;

    const float* ib = d_ebuf2p + (long)b * C2 * (E2R * E2W);

#pragma unroll 1
    for (int h = 0; h < 2; h++) {
        // stage ic-half weights: oc-major slice [o][576h + k]
        if (h) __syncthreads();
        for (int idx = threadIdx.x; idx < 16 * HEAD1_KH; idx += 128) {
            const int o = idx / HEAD1_KH;
            const int k = idx - o * HEAD1_KH;
            wsm[k][o] = wbase[o * HEAD1_K + h * HEAD1_KH + k];
        }
        __syncthreads();

        const int ic0 = h * 64;
#pragma unroll 1
        for (int ici = 0; ici < 64; ici++) {
            const float* xc = ib + (long)(ic0 + ici) * (E2R * E2W);
            float W3[3][8];
#pragma unroll
            for (int r = 0; r < 3; r++) {
                const float4 a = *(const float4*)(xc + (oy + r) * E2W + 4 * l);
                const float4 c = *(const float4*)(xc + (oy + r) * E2W + 4 * l + 4);
                W3[r][0] = a.x; W3[r][1] = a.y; W3[r][2] = a.z; W3[r][3] = a.w;
                W3[r][4] = c.x; W3[r][5] = c.y; W3[r][6] = c.z; W3[r][7] = c.w;
            }
#pragma unroll
            for (int ky = 0; ky < 3; ky++) {
                const int kb = (ici * 3 + ky) * 3;
#pragma unroll
                for (int kx = 0; kx < 3; kx++) {
                    const ulonglong2* wp = (const ulonglong2*)wsm[kb + kx];
                    const ulonglong2 wA = wp[0], wB = wp[1], wC = wp[2], wD = wp[3];
#pragma unroll
                    for (int p = 0; p < 4; p++) {
                        const unsigned long long vv = pack2(W3[ky][p + kx]);
                        FFMA2_16(acc[p], vv, wA, wB, wC, wD);
                    }
                }
            }
        }
    }

#pragma unroll
    for (int j = 0; j < 8; j++) {
        const int oca = ocg * 16 + 2 * j;
        const int ocb = oca + 1;
        const float ba = b_all[e * C2 + oca];
        const float bb = b_all[e * C2 + ocb];
        float4 va, vb;
        va.x = fmaxf(f2lo(acc[0][j]) + ba, 0.f);
        va.y = fmaxf(f2lo(acc[1][j]) + ba, 0.f);
        va.z = fmaxf(f2lo(acc[2][j]) + ba, 0.f);
        va.w = fmaxf(f2lo(acc[3][j]) + ba, 0.f);
        vb.x = fmaxf(f2hi(acc[0][j]) + bb, 0.f);
        vb.y = fmaxf(f2hi(acc[1][j]) + bb, 0.f);
        vb.z = fmaxf(f2hi(acc[2][j]) + bb, 0.f);
        vb.w = fmaxf(f2hi(acc[3][j]) + bb, 0.f);
        *(float4*)(d_ebuf3 + ((long)(b * C2 + oca) * H2 + oy) * W2 + 4 * l) = va;
        *(float4*)(d_ebuf3 + ((long)(b * C2 + ocb) * H2 + oy) * W2 + 4 * l) = vb;
    }
}

// ---------------------------------------------------------------------------
// Kernel 6: 1x1 conv 128 -> 5 + bias, scatter into (hm, wh, reg) layout.
// ---------------------------------------------------------------------------
__global__ void __launch_bounds__(128)
head2_kernel(const float* __restrict__ w_all,
             const float* __restrict__ b_all,
             float* __restrict__ out)
{
    const int oy = blockIdx.x;
    const int b  = blockIdx.y;
    const int ox = threadIdx.x;
    const int e  = d_eidx[b];

    __shared__ __align__(16) float ws[C2][8];
    for (int idx = threadIdx.x; idx < 5 * C2; idx += 128) {
        const int j = idx / C2, ic = idx - j * C2;
        ws[ic][j] = w_all[(long)e * 5 * C2 + idx];
    }
    __syncthreads();

    float acc[5] = {0.f, 0.f, 0.f, 0.f, 0.f};
    const float* ib = d_ebuf3 + (long)b * C2 * H2 * W2 + oy * W2 + ox;
    for (int ic = 0; ic < C2; ic++) {
        const float v = __ldg(ib + ic * (H2 * W2));
        const float4 w4 = *(const float4*)ws[ic];
        acc[0] += v * w4.x;
        acc[1] += v * w4.y;
        acc[2] += v * w4.z;
        acc[3] += v * w4.w;
        acc[4] += v * ws[ic][4];
    }

    const int p  = oy * W2 + ox;
    const int HW = H2 * W2;
    const float* bb = b_all + e * 5;
    out[b * HW + p]                        = acc[0] + bb[0];
    out[B * HW + (b * 2 + 0) * HW + p]     = acc[1] + bb[1];
    out[B * HW + (b * 2 + 1) * HW + p]     = acc[2] + bb[2];
    out[3 * B * HW + (b * 2 + 0) * HW + p] = acc[3] + bb[3];
    out[3 * B * HW + (b * 2 + 1) * HW + p] = acc[4] + bb[4];
}

// ---------------------------------------------------------------------------
// Launch
// ---------------------------------------------------------------------------
extern "C" void kernel_launch(void* const* d_in, const int* in_sizes, int n_in,
                              void* d_out, int out_size)
{
    const float* x        = (const float*)d_in[0];
    const float* g_conv_w = (const float*)d_in[1];
    const float* g_gamma  = (const float*)d_in[2];
    const float* g_beta   = (const float*)d_in[3];
    const float* g_mean   = (const float*)d_in[4];
    const float* g_var    = (const float*)d_in[5];
    const float* g_fc_w   = (const float*)d_in[6];
    const float* g_fc_b   = (const float*)d_in[7];
    const float* e_conv1  = (const float*)d_in[8];
    const float* e_conv2  = (const float*)d_in[9];
    const float* e_hw1    = (const float*)d_in[10];
    const float* e_hb1    = (const float*)d_in[11];
    const float* e_hw2    = (const float*)d_in[12];
    const float* e_hb2    = (const float*)d_in[13];
    float* out = (float*)d_out;

    // 0. Pad/deinterleave input + zero activation halos (single launch)
    prep_kernel<<<PREP_E2, 256>>>(x);
    // 1. Gating conv (7x7 s2) + BN + ReLU
    conv7x7_kernel<true><<<dim3(128, 4, B), 128>>>(g_conv_w, g_gamma, g_beta, g_mean, g_var);
    // 2. Maxpool + global average
    pool_mean_kernel<<<B * C1, 256>>>();
    // 3. Logits, top-1 expert selection, aux loss
    gate_finalize_kernel<<<1, 32>>>(g_fc_w, g_fc_b, out + (out_size - 1));
    // 4. Selected expert conv1 (7x7 s2) + ReLU -> ebuf1p (deinterleaved)
    conv7x7_kernel<false><<<dim3(128, 4, B), 128>>>(e_conv1, nullptr, nullptr, nullptr, nullptr);
    // 5. Expert conv2 (3x3 s2) + ReLU -> ebuf2p (padded)
    conv2_kernel<<<dim3(32, 8, B), 128>>>(e_conv2);
    // 6. Head conv1 (3x3 s1) + bias + ReLU -> ebuf3 (two-pass weight staging)
    head1_kernel<<<dim3(32, 8, B), 128>>>(e_hw1, e_hb1);
    // 7. Head conv2 (1x1) + bias, scattered to (hm, wh, reg)
    head2_kernel<<<dim3(128, B), 128>>>(e_hw2, e_hb2, out);
}